// round 11
// baseline (speedup 1.0000x reference)
#include <cuda_runtime.h>
#include <cuda_fp16.h>
#include <stdint.h>

#define B_USERS     4096
#define D_DIM       64
#define NNZ_CNT     204800
#define N_PAIRS     1048576
#define NUM_ITEMS_C 100000

#define DECODE_BLOCKS (N_PAIRS * 2 / 256)            // 8192 (4 pairs per 8-lane group)
#define ITEM_SEG      100352                          // items segment, padded to /256
#define USER_SEG      (B_USERS * 16)                  // 65536
#define TAIL_THREADS  (ITEM_SEG + USER_SEG)           // 165888
#define TAIL_BLOCKS   (TAIL_THREADS / 256)            // 648
#define PREDE_THREADS (NUM_ITEMS_C * D_DIM / 16)      // 400000 (4 threads/row) — NOT /256!
#define PREDE_BLOCKS  ((PREDE_THREADS + 255) / 256)   // 1563 (ceil)

// Scratch (no cudaMalloc allowed)
__device__ float         g_hidden[B_USERS * D_DIM];
__device__ __half        g_hidden_h[B_USERS * D_DIM];
__device__ __half        g_de_h[NUM_ITEMS_C * D_DIM];
__device__ float         g_item_reg[NUM_ITEMS_C];
__device__ unsigned char g_mask[NUM_ITEMS_C];

// ---------------- Threefry-2x32 (JAX partitionable path) ----------------
__device__ __forceinline__ uint32_t rotl32(uint32_t x, int r) {
    return (x << r) | (x >> (32 - r));
}

__device__ __forceinline__ uint32_t threefry_bits(uint32_t ctr_lo) {
    const uint32_t ks0 = 0u, ks1 = 42u;
    const uint32_t ks2 = ks0 ^ ks1 ^ 0x1BD11BDAu;
    uint32_t x0 = 0u  + ks0;
    uint32_t x1 = ctr_lo + ks1;

    x0 += x1; x1 = rotl32(x1, 13); x1 ^= x0;
    x0 += x1; x1 = rotl32(x1, 15); x1 ^= x0;
    x0 += x1; x1 = rotl32(x1, 26); x1 ^= x0;
    x0 += x1; x1 = rotl32(x1,  6); x1 ^= x0;
    x0 += ks1; x1 += ks2 + 1u;
    x0 += x1; x1 = rotl32(x1, 17); x1 ^= x0;
    x0 += x1; x1 = rotl32(x1, 29); x1 ^= x0;
    x0 += x1; x1 = rotl32(x1, 16); x1 ^= x0;
    x0 += x1; x1 = rotl32(x1, 24); x1 ^= x0;
    x0 += ks2; x1 += ks0 + 2u;
    x0 += x1; x1 = rotl32(x1, 13); x1 ^= x0;
    x0 += x1; x1 = rotl32(x1, 15); x1 ^= x0;
    x0 += x1; x1 = rotl32(x1, 26); x1 ^= x0;
    x0 += x1; x1 = rotl32(x1,  6); x1 ^= x0;
    x0 += ks0; x1 += ks1 + 3u;
    x0 += x1; x1 = rotl32(x1, 17); x1 ^= x0;
    x0 += x1; x1 = rotl32(x1, 29); x1 ^= x0;
    x0 += x1; x1 = rotl32(x1, 16); x1 ^= x0;
    x0 += x1; x1 = rotl32(x1, 24); x1 ^= x0;
    x0 += ks1; x1 += ks2 + 4u;
    x0 += x1; x1 = rotl32(x1, 13); x1 ^= x0;
    x0 += x1; x1 = rotl32(x1, 15); x1 ^= x0;
    x0 += x1; x1 = rotl32(x1, 26); x1 ^= x0;
    x0 += x1; x1 = rotl32(x1,  6); x1 ^= x0;
    x0 += ks2; x1 += ks0 + 5u;

    return x0 ^ x1;
}

// ---------------- fp16 pack helpers ----------------
__device__ __forceinline__ uint32_t pack_h2(float a, float b) {
    __half2 h = __floats2half2_rn(a, b);
    return *reinterpret_cast<uint32_t*>(&h);
}
__device__ __forceinline__ uint4 pack_8(float4 a, float4 b) {
    return make_uint4(pack_h2(a.x, a.y), pack_h2(a.z, a.w),
                      pack_h2(b.x, b.y), pack_h2(b.z, b.w));
}
__device__ __forceinline__ float sumsq4(float4 v) {
    return v.x * v.x + v.y * v.y + v.z * v.z + v.w * v.w;
}

// ---------------- Stream B: de convert + item reg norms ----------------
// 4 threads per item row, each handling 16 elems of de and en.
__global__ void __launch_bounds__(256) k_pre_de(
        const float* __restrict__ de_emb,
        const float* __restrict__ en_emb,
        const float* __restrict__ de_bias) {
    int idx = blockIdx.x * blockDim.x + threadIdx.x;
    if (idx >= PREDE_THREADS) return;     // grid is ceil-div; guard the tail
    int row = idx >> 2;
    int l4  = idx & 3;

    const float4* dp = (const float4*)de_emb + idx * 4;
    const float4* ep = (const float4*)en_emb + idx * 4;
    float4 d0 = __ldg(dp + 0), d1 = __ldg(dp + 1), d2 = __ldg(dp + 2), d3 = __ldg(dp + 3);
    float4 e0 = __ldg(ep + 0), e1 = __ldg(ep + 1), e2 = __ldg(ep + 2), e3 = __ldg(ep + 3);

    ((uint4*)g_de_h)[idx * 2]     = pack_8(d0, d1);
    ((uint4*)g_de_h)[idx * 2 + 1] = pack_8(d2, d3);

    float c = sumsq4(d0) + sumsq4(d1) + sumsq4(d2) + sumsq4(d3)
            + sumsq4(e0) + sumsq4(e1) + sumsq4(e2) + sumsq4(e3);
    // 4-lane row reduce; all threads in a 4-group are active together
    // (PREDE_THREADS is a multiple of 4, guard cuts whole rows only)
    c += __shfl_xor_sync(0xffffffffu, c, 1);
    c += __shfl_xor_sync(0xffffffffu, c, 2);
    if (l4 == 0) {
        float bb = __ldg(de_bias + row);
        g_item_reg[row] = c + bb * bb;
    }
}

// ---------------- Stream A ----------------
__global__ void k_hinit(const int* __restrict__ user_ids,
                        const float* __restrict__ user_emb,
                        const float* __restrict__ en_offset,
                        float* reg_out) {
    int idx = blockIdx.x * blockDim.x + threadIdx.x;   // exact: B*D/4 = 65536
    int bu = idx >> 4;
    int d4 = idx & 15;
    float4 u = __ldg((const float4*)user_emb + (size_t)__ldg(user_ids + bu) * 16 + d4);
    float4 o = __ldg((const float4*)en_offset + d4);
    ((float4*)g_hidden)[idx] = make_float4(u.x + o.x, u.y + o.y, u.z + o.z, u.w + o.w);

    if (idx * 4 < NUM_ITEMS_C) ((uint32_t*)g_mask)[idx] = 0;
    if (idx == 0 && reg_out) *reg_out = 0.0f;
}

__global__ void k_scatter(const int* __restrict__ sp_row,
                          const int* __restrict__ sp_col,
                          const float* __restrict__ en_emb,
                          const int* __restrict__ bat_items) {
    int t    = blockIdx.x * blockDim.x + threadIdx.x;
    int i    = t >> 4;
    int lane = t & 15;
    int wl   = threadIdx.x & 31;

    uint32_t keep = 0;
    if (lane == 0) {
        uint32_t bits = threefry_bits((uint32_t)i);
        float u = __uint_as_float((bits >> 9) | 0x3f800000u) - 1.0f;
        keep = (u < 0.8f) ? 1u : 0u;
    }
    keep = __shfl_sync(0xffffffffu, keep, wl & 16, 32);
    int item = (t < N_PAIRS) ? __ldg(bat_items + t) : -1;

    cudaGridDependencySynchronize();   // k_hinit complete (hidden + mask zero)

    if (item >= 0) g_mask[item] = 1;
    if (!keep) return;

    int row = __ldg(sp_row + i);
    int col = __ldg(sp_col + i);
    float4 e = __ldg((const float4*)en_emb + (size_t)col * 16 + lane);
    float4 v = make_float4(1.25f * e.x, 1.25f * e.y, 1.25f * e.z, 1.25f * e.w);
    atomicAdd((float4*)(g_hidden + (size_t)row * 64 + lane * 4), v);
}

__global__ void k_tanh() {
    cudaGridDependencySynchronize();
    int idx = blockIdx.x * blockDim.x + threadIdx.x;   // exact: B*D/8
    float4 a = ((const float4*)g_hidden)[idx * 2];
    float4 b = ((const float4*)g_hidden)[idx * 2 + 1];
    a = make_float4(tanhf(a.x), tanhf(a.y), tanhf(a.z), tanhf(a.w));
    b = make_float4(tanhf(b.x), tanhf(b.y), tanhf(b.z), tanhf(b.w));
    ((uint4*)g_hidden_h)[idx] = pack_8(a, b);
}

// ---------------- K4: decode + tiny reg tail (NORMAL launch) ----------------
__device__ __forceinline__ float dot8h(uint4 hv, uint4 ev) {
    float acc = 0.0f;
    const uint32_t* hw = (const uint32_t*)&hv;
    const uint32_t* ew = (const uint32_t*)&ev;
#pragma unroll
    for (int i = 0; i < 4; i++) {
        float2 f = __half22float2(*(const __half2*)&hw[i]);
        float2 g = __half22float2(*(const __half2*)&ew[i]);
        acc += f.x * g.x + f.y * g.y;
    }
    return acc;
}

__global__ void __launch_bounds__(256) k_decode_reg(
        const int* __restrict__ bat_idx,
        const int* __restrict__ bat_items,
        const float* __restrict__ de_bias,
        const float* __restrict__ en_offset,
        const float* __restrict__ user_emb,
        const int*   __restrict__ user_ids,
        float* __restrict__ out,
        float* __restrict__ reg_out) {
    if (blockIdx.x < DECODE_BLOCKS) {
        int t = blockIdx.x * blockDim.x + threadIdx.x;
        int g = t >> 3;             // group handles pairs 4g..4g+3
        int l = t & 7;

        int4 bb = __ldg((const int4*)bat_idx + g);
        int4 ii = __ldg((const int4*)bat_items + g);

        uint4 h0 = ((const uint4*)g_hidden_h + (size_t)bb.x * 8)[l];
        uint4 h1 = ((const uint4*)g_hidden_h + (size_t)bb.y * 8)[l];
        uint4 h2 = ((const uint4*)g_hidden_h + (size_t)bb.z * 8)[l];
        uint4 h3 = ((const uint4*)g_hidden_h + (size_t)bb.w * 8)[l];
        uint4 e0 = ((const uint4*)g_de_h + (size_t)ii.x * 8)[l];
        uint4 e1 = ((const uint4*)g_de_h + (size_t)ii.y * 8)[l];
        uint4 e2 = ((const uint4*)g_de_h + (size_t)ii.z * 8)[l];
        uint4 e3 = ((const uint4*)g_de_h + (size_t)ii.w * 8)[l];

        float p0 = dot8h(h0, e0);
        float p1 = dot8h(h1, e1);
        float p2 = dot8h(h2, e2);
        float p3 = dot8h(h3, e3);
#pragma unroll
        for (int s = 1; s <= 4; s <<= 1) {
            p0 += __shfl_xor_sync(0xffffffffu, p0, s);
            p1 += __shfl_xor_sync(0xffffffffu, p1, s);
            p2 += __shfl_xor_sync(0xffffffffu, p2, s);
            p3 += __shfl_xor_sync(0xffffffffu, p3, s);
        }
        if (l == 0) {
            float4 r = make_float4(p0 + __ldg(de_bias + ii.x),
                                   p1 + __ldg(de_bias + ii.y),
                                   p2 + __ldg(de_bias + ii.z),
                                   p3 + __ldg(de_bias + ii.w));
            ((float4*)out)[g] = r;
        }
    } else {
        __shared__ float bacc;
        if (threadIdx.x == 0) bacc = 0.0f;
        __syncthreads();

        int t = (blockIdx.x - DECODE_BLOCKS) * blockDim.x + threadIdx.x;
        float c = 0.0f;
        if (t < NUM_ITEMS_C) {
            c = g_mask[t] ? g_item_reg[t] : 0.0f;
            if (t == 0) {
                for (int k = 0; k < D_DIM; k++) {
                    float o = __ldg(en_offset + k);
                    c += o * o;
                }
            }
        } else if (t >= ITEM_SEG && t < TAIL_THREADS) {
            int r = t - ITEM_SEG;
            int b = r >> 4, lane = r & 15;
            float4 u = __ldg((const float4*)user_emb + (size_t)__ldg(user_ids + b) * 16 + lane);
            c = sumsq4(u);
        }
#pragma unroll
        for (int s = 1; s <= 16; s <<= 1) c += __shfl_xor_sync(0xffffffffu, c, s);
        if ((threadIdx.x & 31) == 0 && c != 0.0f) atomicAdd(&bacc, c);
        __syncthreads();
        if (threadIdx.x == 0 && bacc != 0.0f && reg_out) atomicAdd(reg_out, 0.5f * bacc);
    }
}

// ---------------- launch ----------------
static void launch_pdl(void* fn, dim3 grid, void** args) {
    cudaLaunchConfig_t cfg = {};
    cfg.gridDim = grid;
    cfg.blockDim = dim3(256);
    cfg.dynamicSmemBytes = 0;
    cfg.stream = 0;
    cudaLaunchAttribute attr[1];
    attr[0].id = cudaLaunchAttributeProgrammaticStreamSerialization;
    attr[0].val.programmaticStreamSerializationAllowed = 1;
    cfg.attrs = attr;
    cfg.numAttrs = 1;
    cudaLaunchKernelExC(&cfg, fn, args);
}

extern "C" void kernel_launch(void* const* d_in, const int* in_sizes, int n_in,
                              void* d_out, int out_size) {
    const int*   user_ids  = (const int*)d_in[0];
    const int*   bat_idx   = (const int*)d_in[1];
    const int*   sp_row    = (const int*)d_in[2];
    const int*   sp_col    = (const int*)d_in[3];
    const int*   bat_items = (const int*)d_in[4];
    const float* en_emb    = (const float*)d_in[5];
    const float* en_offset = (const float*)d_in[6];
    const float* de_emb    = (const float*)d_in[7];
    const float* de_bias   = (const float*)d_in[8];
    const float* user_emb  = (const float*)d_in[9];
    float* out = (float*)d_out;
    float* reg_out = (out_size > N_PAIRS) ? (out + N_PAIRS) : nullptr;

    static cudaStream_t sB = nullptr;
    static cudaEvent_t evFork = nullptr, evJoin = nullptr;
    if (!sB) {
        cudaStreamCreateWithFlags(&sB, cudaStreamNonBlocking);
        cudaEventCreateWithFlags(&evFork, cudaEventDisableTiming);
        cudaEventCreateWithFlags(&evJoin, cudaEventDisableTiming);
    }

    // Fork: stream B does the DRAM-heavy de/en pass
    cudaEventRecord(evFork, 0);
    cudaStreamWaitEvent(sB, evFork, 0);
    k_pre_de<<<PREDE_BLOCKS, 256, 0, sB>>>(de_emb, en_emb, de_bias);
    cudaEventRecord(evJoin, sB);

    // Stream A: hidden chain (PDL-linked, same-stream only)
    k_hinit<<<(B_USERS * D_DIM / 4) / 256, 256>>>(user_ids, user_emb, en_offset, reg_out);
    {
        void* args[] = { (void*)&sp_row, (void*)&sp_col, (void*)&en_emb, (void*)&bat_items };
        launch_pdl((void*)k_scatter, dim3(NNZ_CNT * 16 / 256), args);
    }
    {
        void* args[] = {};
        launch_pdl((void*)k_tanh, dim3(B_USERS * D_DIM / 8 / 256), args);
    }

    // Join B, then decode as a NORMAL launch
    cudaStreamWaitEvent(0, evJoin, 0);
    k_decode_reg<<<DECODE_BLOCKS + TAIL_BLOCKS, 256>>>(
        bat_idx, bat_items, de_bias, en_offset, user_emb, user_ids, out, reg_out);
}

// round 12
// speedup vs baseline: 1.0397x; 1.0397x over previous
#include <cuda_runtime.h>
#include <cuda_fp16.h>
#include <stdint.h>

#define B_USERS     4096
#define D_DIM       64
#define NNZ_CNT     204800
#define N_PAIRS     1048576
#define NUM_ITEMS_C 100000

#define DECODE_BLOCKS (N_PAIRS * 2 / 256)            // 8192 (4 pairs per 8-lane group)
#define ITEM_SEG      100352                          // items segment, padded to /256
#define USER_SEG      (B_USERS * 16)                  // 65536
#define TAIL_THREADS  (ITEM_SEG + USER_SEG)           // 165888
#define TAIL_BLOCKS   (TAIL_THREADS / 256)            // 648
#define PRE_THREADS   (NUM_ITEMS_C * D_DIM / 16)      // 400000 (4 threads/row)
#define PRE_BLOCKS    ((PRE_THREADS + 255) / 256)     // 1563 (ceil!)

// Scratch (no cudaMalloc allowed)
__device__ float         g_hidden[B_USERS * D_DIM];
__device__ __half        g_hidden_h[B_USERS * D_DIM];
__device__ __half        g_de_h[NUM_ITEMS_C * D_DIM];
__device__ float         g_item_reg[NUM_ITEMS_C];
__device__ unsigned char g_mask[NUM_ITEMS_C];

// ---------------- Threefry-2x32 (JAX partitionable path) ----------------
__device__ __forceinline__ uint32_t rotl32(uint32_t x, int r) {
    return (x << r) | (x >> (32 - r));
}

__device__ __forceinline__ uint32_t threefry_bits(uint32_t ctr_lo) {
    const uint32_t ks0 = 0u, ks1 = 42u;
    const uint32_t ks2 = ks0 ^ ks1 ^ 0x1BD11BDAu;
    uint32_t x0 = 0u  + ks0;
    uint32_t x1 = ctr_lo + ks1;

    x0 += x1; x1 = rotl32(x1, 13); x1 ^= x0;
    x0 += x1; x1 = rotl32(x1, 15); x1 ^= x0;
    x0 += x1; x1 = rotl32(x1, 26); x1 ^= x0;
    x0 += x1; x1 = rotl32(x1,  6); x1 ^= x0;
    x0 += ks1; x1 += ks2 + 1u;
    x0 += x1; x1 = rotl32(x1, 17); x1 ^= x0;
    x0 += x1; x1 = rotl32(x1, 29); x1 ^= x0;
    x0 += x1; x1 = rotl32(x1, 16); x1 ^= x0;
    x0 += x1; x1 = rotl32(x1, 24); x1 ^= x0;
    x0 += ks2; x1 += ks0 + 2u;
    x0 += x1; x1 = rotl32(x1, 13); x1 ^= x0;
    x0 += x1; x1 = rotl32(x1, 15); x1 ^= x0;
    x0 += x1; x1 = rotl32(x1, 26); x1 ^= x0;
    x0 += x1; x1 = rotl32(x1,  6); x1 ^= x0;
    x0 += ks0; x1 += ks1 + 3u;
    x0 += x1; x1 = rotl32(x1, 17); x1 ^= x0;
    x0 += x1; x1 = rotl32(x1, 29); x1 ^= x0;
    x0 += x1; x1 = rotl32(x1, 16); x1 ^= x0;
    x0 += x1; x1 = rotl32(x1, 24); x1 ^= x0;
    x0 += ks1; x1 += ks2 + 4u;
    x0 += x1; x1 = rotl32(x1, 13); x1 ^= x0;
    x0 += x1; x1 = rotl32(x1, 15); x1 ^= x0;
    x0 += x1; x1 = rotl32(x1, 26); x1 ^= x0;
    x0 += x1; x1 = rotl32(x1,  6); x1 ^= x0;
    x0 += ks2; x1 += ks0 + 5u;

    return x0 ^ x1;
}

// ---------------- fp16 pack helpers ----------------
__device__ __forceinline__ uint32_t pack_h2(float a, float b) {
    __half2 h = __floats2half2_rn(a, b);
    return *reinterpret_cast<uint32_t*>(&h);
}
__device__ __forceinline__ uint4 pack_8(float4 a, float4 b) {
    return make_uint4(pack_h2(a.x, a.y), pack_h2(a.z, a.w),
                      pack_h2(b.x, b.y), pack_h2(b.z, b.w));
}
__device__ __forceinline__ float sumsq4(float4 v) {
    return v.x * v.x + v.y * v.y + v.z * v.z + v.w * v.w;
}

// ---------------- K1: fused preamble (single stream) ----------------
// 4 threads/item row: de convert (8 independent LDG.128 across de+en),
// item reg norms, plus hidden init + mask/reg zero for low idx.
__global__ void __launch_bounds__(256) k_pre(
        const float* __restrict__ de_emb,
        const float* __restrict__ en_emb,
        const float* __restrict__ de_bias,
        const int*   __restrict__ user_ids,
        const float* __restrict__ user_emb,
        const float* __restrict__ en_offset,
        float* reg_out) {
    int idx = blockIdx.x * blockDim.x + threadIdx.x;
    if (idx >= PRE_THREADS) return;     // ceil-div grid; whole 4-groups cut only
    int row = idx >> 2;
    int l4  = idx & 3;

    const float4* dp = (const float4*)de_emb + idx * 4;
    const float4* ep = (const float4*)en_emb + idx * 4;
    float4 d0 = __ldg(dp + 0), d1 = __ldg(dp + 1), d2 = __ldg(dp + 2), d3 = __ldg(dp + 3);
    float4 e0 = __ldg(ep + 0), e1 = __ldg(ep + 1), e2 = __ldg(ep + 2), e3 = __ldg(ep + 3);

    ((uint4*)g_de_h)[idx * 2]     = pack_8(d0, d1);
    ((uint4*)g_de_h)[idx * 2 + 1] = pack_8(d2, d3);

    float c = sumsq4(d0) + sumsq4(d1) + sumsq4(d2) + sumsq4(d3)
            + sumsq4(e0) + sumsq4(e1) + sumsq4(e2) + sumsq4(e3);
    c += __shfl_xor_sync(0xffffffffu, c, 1);
    c += __shfl_xor_sync(0xffffffffu, c, 2);
    if (l4 == 0) {
        float bb = __ldg(de_bias + row);
        g_item_reg[row] = c + bb * bb;
    }

    // hidden init for idx < B*D/4
    if (idx < B_USERS * D_DIM / 4) {
        int bu = idx >> 4;
        int d4 = idx & 15;
        float4 u = __ldg((const float4*)user_emb + (size_t)__ldg(user_ids + bu) * 16 + d4);
        float4 o = __ldg((const float4*)en_offset + d4);
        ((float4*)g_hidden)[idx] = make_float4(u.x + o.x, u.y + o.y, u.z + o.z, u.w + o.w);
    }
    if (idx * 4 < NUM_ITEMS_C) ((uint32_t*)g_mask)[idx] = 0;
    if (idx == 0 && reg_out) *reg_out = 0.0f;
}

// ---------------- K2: scatter + item-mask ----------------
__global__ void k_scatter(const int* __restrict__ sp_row,
                          const int* __restrict__ sp_col,
                          const float* __restrict__ en_emb,
                          const int* __restrict__ bat_items) {
    int t    = blockIdx.x * blockDim.x + threadIdx.x;
    int i    = t >> 4;
    int lane = t & 15;
    int wl   = threadIdx.x & 31;

    uint32_t keep = 0;
    if (lane == 0) {
        uint32_t bits = threefry_bits((uint32_t)i);
        float u = __uint_as_float((bits >> 9) | 0x3f800000u) - 1.0f;
        keep = (u < 0.8f) ? 1u : 0u;
    }
    keep = __shfl_sync(0xffffffffu, keep, wl & 16, 32);
    int item = (t < N_PAIRS) ? __ldg(bat_items + t) : -1;

    cudaGridDependencySynchronize();   // K1 complete

    if (item >= 0) g_mask[item] = 1;
    if (!keep) return;

    int row = __ldg(sp_row + i);
    int col = __ldg(sp_col + i);
    float4 e = __ldg((const float4*)en_emb + (size_t)col * 16 + lane);
    float4 v = make_float4(1.25f * e.x, 1.25f * e.y, 1.25f * e.z, 1.25f * e.w);
    atomicAdd((float4*)(g_hidden + (size_t)row * 64 + lane * 4), v);
}

// ---------------- K3: tanh + fp16 copy ----------------
__global__ void k_tanh() {
    cudaGridDependencySynchronize();
    int idx = blockIdx.x * blockDim.x + threadIdx.x;   // exact: B*D/8
    float4 a = ((const float4*)g_hidden)[idx * 2];
    float4 b = ((const float4*)g_hidden)[idx * 2 + 1];
    a = make_float4(tanhf(a.x), tanhf(a.y), tanhf(a.z), tanhf(a.w));
    b = make_float4(tanhf(b.x), tanhf(b.y), tanhf(b.z), tanhf(b.w));
    ((uint4*)g_hidden_h)[idx] = pack_8(a, b);
}

// ---------------- K4: decode + tiny reg tail ----------------
__device__ __forceinline__ float dot8h(uint4 hv, uint4 ev) {
    float acc = 0.0f;
    const uint32_t* hw = (const uint32_t*)&hv;
    const uint32_t* ew = (const uint32_t*)&ev;
#pragma unroll
    for (int i = 0; i < 4; i++) {
        float2 f = __half22float2(*(const __half2*)&hw[i]);
        float2 g = __half22float2(*(const __half2*)&ew[i]);
        acc += f.x * g.x + f.y * g.y;
    }
    return acc;
}

__global__ void __launch_bounds__(256) k_decode_reg(
        const int* __restrict__ bat_idx,
        const int* __restrict__ bat_items,
        const float* __restrict__ de_bias,
        const float* __restrict__ en_offset,
        const float* __restrict__ user_emb,
        const int*   __restrict__ user_ids,
        float* __restrict__ out,
        float* __restrict__ reg_out) {
    if (blockIdx.x < DECODE_BLOCKS) {
        int t = blockIdx.x * blockDim.x + threadIdx.x;
        int g = t >> 3;             // group handles pairs 4g..4g+3
        int l = t & 7;

        int4 bb = __ldg((const int4*)bat_idx + g);
        int4 ii = __ldg((const int4*)bat_items + g);
        cudaGridDependencySynchronize();   // hidden_h + de_h ready (same-stream chain)

        uint4 h0 = ((const uint4*)g_hidden_h + (size_t)bb.x * 8)[l];
        uint4 h1 = ((const uint4*)g_hidden_h + (size_t)bb.y * 8)[l];
        uint4 h2 = ((const uint4*)g_hidden_h + (size_t)bb.z * 8)[l];
        uint4 h3 = ((const uint4*)g_hidden_h + (size_t)bb.w * 8)[l];
        uint4 e0 = ((const uint4*)g_de_h + (size_t)ii.x * 8)[l];
        uint4 e1 = ((const uint4*)g_de_h + (size_t)ii.y * 8)[l];
        uint4 e2 = ((const uint4*)g_de_h + (size_t)ii.z * 8)[l];
        uint4 e3 = ((const uint4*)g_de_h + (size_t)ii.w * 8)[l];

        float p0 = dot8h(h0, e0);
        float p1 = dot8h(h1, e1);
        float p2 = dot8h(h2, e2);
        float p3 = dot8h(h3, e3);
#pragma unroll
        for (int s = 1; s <= 4; s <<= 1) {
            p0 += __shfl_xor_sync(0xffffffffu, p0, s);
            p1 += __shfl_xor_sync(0xffffffffu, p1, s);
            p2 += __shfl_xor_sync(0xffffffffu, p2, s);
            p3 += __shfl_xor_sync(0xffffffffu, p3, s);
        }
        if (l == 0) {
            float4 r = make_float4(p0 + __ldg(de_bias + ii.x),
                                   p1 + __ldg(de_bias + ii.y),
                                   p2 + __ldg(de_bias + ii.z),
                                   p3 + __ldg(de_bias + ii.w));
            ((float4*)out)[g] = r;
        }
    } else {
        cudaGridDependencySynchronize();
        __shared__ float bacc;
        if (threadIdx.x == 0) bacc = 0.0f;
        __syncthreads();

        int t = (blockIdx.x - DECODE_BLOCKS) * blockDim.x + threadIdx.x;
        float c = 0.0f;
        if (t < NUM_ITEMS_C) {
            c = g_mask[t] ? g_item_reg[t] : 0.0f;
            if (t == 0) {
                for (int k = 0; k < D_DIM; k++) {
                    float o = __ldg(en_offset + k);
                    c += o * o;
                }
            }
        } else if (t >= ITEM_SEG && t < TAIL_THREADS) {
            int r = t - ITEM_SEG;
            int b = r >> 4, lane = r & 15;
            float4 u = __ldg((const float4*)user_emb + (size_t)__ldg(user_ids + b) * 16 + lane);
            c = sumsq4(u);
        }
#pragma unroll
        for (int s = 1; s <= 16; s <<= 1) c += __shfl_xor_sync(0xffffffffu, c, s);
        if ((threadIdx.x & 31) == 0 && c != 0.0f) atomicAdd(&bacc, c);
        __syncthreads();
        if (threadIdx.x == 0 && bacc != 0.0f && reg_out) atomicAdd(reg_out, 0.5f * bacc);
    }
}

// ---------------- launch ----------------
static void launch_pdl(void* fn, dim3 grid, void** args) {
    cudaLaunchConfig_t cfg = {};
    cfg.gridDim = grid;
    cfg.blockDim = dim3(256);
    cfg.dynamicSmemBytes = 0;
    cfg.stream = 0;
    cudaLaunchAttribute attr[1];
    attr[0].id = cudaLaunchAttributeProgrammaticStreamSerialization;
    attr[0].val.programmaticStreamSerializationAllowed = 1;
    cfg.attrs = attr;
    cfg.numAttrs = 1;
    cudaLaunchKernelExC(&cfg, fn, args);
}

extern "C" void kernel_launch(void* const* d_in, const int* in_sizes, int n_in,
                              void* d_out, int out_size) {
    const int*   user_ids  = (const int*)d_in[0];
    const int*   bat_idx   = (const int*)d_in[1];
    const int*   sp_row    = (const int*)d_in[2];
    const int*   sp_col    = (const int*)d_in[3];
    const int*   bat_items = (const int*)d_in[4];
    const float* en_emb    = (const float*)d_in[5];
    const float* en_offset = (const float*)d_in[6];
    const float* de_emb    = (const float*)d_in[7];
    const float* de_bias   = (const float*)d_in[8];
    const float* user_emb  = (const float*)d_in[9];
    float* out = (float*)d_out;
    float* reg_out = (out_size > N_PAIRS) ? (out + N_PAIRS) : nullptr;

    // Single stream, PDL-chained (validated topology from R8)
    k_pre<<<PRE_BLOCKS, 256>>>(de_emb, en_emb, de_bias, user_ids,
                               user_emb, en_offset, reg_out);
    {
        void* args[] = { (void*)&sp_row, (void*)&sp_col, (void*)&en_emb, (void*)&bat_items };
        launch_pdl((void*)k_scatter, dim3(NNZ_CNT * 16 / 256), args);
    }
    {
        void* args[] = {};
        launch_pdl((void*)k_tanh, dim3(B_USERS * D_DIM / 8 / 256), args);
    }
    {
        void* args[] = { (void*)&bat_idx, (void*)&bat_items, (void*)&de_bias,
                         (void*)&en_offset, (void*)&user_emb, (void*)&user_ids,
                         (void*)&out, (void*)&reg_out };
        launch_pdl((void*)k_decode_reg, dim3(DECODE_BLOCKS + TAIL_BLOCKS), args);
    }
}

// round 13
// speedup vs baseline: 1.0693x; 1.0284x over previous
#include <cuda_runtime.h>
#include <cuda_fp16.h>
#include <stdint.h>

#define B_USERS     4096
#define D_DIM       64
#define NNZ_CNT     204800
#define N_PAIRS     1048576
#define NUM_ITEMS_C 100000

#define SCAT_BLOCKS  (NNZ_CNT * 16 / 256)            // 12800
#define PRE_BLOCKS   (NUM_ITEMS_C * D_DIM / 8 / 256) // 3125 (exact: 800000 threads)
#define K1_BLOCKS    (SCAT_BLOCKS + PRE_BLOCKS)

#define DECODE_BLOCKS (N_PAIRS * 2 / 256)            // 8192 (4 pairs per 8-lane group)
#define ITEM_SEG      100352                          // items segment, padded
#define USER_SEG      (B_USERS * 16)                  // 65536
#define TAIL_THREADS  (ITEM_SEG + USER_SEG)           // 165888
#define TAIL_BLOCKS   (TAIL_THREADS / 256)            // 648

// Scratch (no cudaMalloc allowed).
// INVARIANT: g_hidden and g_mask are all-zero at every kernel_launch entry.
// Static init establishes it; k_tanh re-zeros g_hidden, the reg tail re-zeros g_mask.
__device__ float         g_hidden[B_USERS * D_DIM];
__device__ __half        g_hidden_h[B_USERS * D_DIM];
__device__ __half        g_de_h[NUM_ITEMS_C * D_DIM];
__device__ float         g_item_reg[NUM_ITEMS_C];
__device__ unsigned char g_mask[NUM_ITEMS_C];

// ---------------- Threefry-2x32 (JAX partitionable path) ----------------
__device__ __forceinline__ uint32_t rotl32(uint32_t x, int r) {
    return (x << r) | (x >> (32 - r));
}

__device__ __forceinline__ uint32_t threefry_bits(uint32_t ctr_lo) {
    const uint32_t ks0 = 0u, ks1 = 42u;
    const uint32_t ks2 = ks0 ^ ks1 ^ 0x1BD11BDAu;
    uint32_t x0 = 0u  + ks0;
    uint32_t x1 = ctr_lo + ks1;

    x0 += x1; x1 = rotl32(x1, 13); x1 ^= x0;
    x0 += x1; x1 = rotl32(x1, 15); x1 ^= x0;
    x0 += x1; x1 = rotl32(x1, 26); x1 ^= x0;
    x0 += x1; x1 = rotl32(x1,  6); x1 ^= x0;
    x0 += ks1; x1 += ks2 + 1u;
    x0 += x1; x1 = rotl32(x1, 17); x1 ^= x0;
    x0 += x1; x1 = rotl32(x1, 29); x1 ^= x0;
    x0 += x1; x1 = rotl32(x1, 16); x1 ^= x0;
    x0 += x1; x1 = rotl32(x1, 24); x1 ^= x0;
    x0 += ks2; x1 += ks0 + 2u;
    x0 += x1; x1 = rotl32(x1, 13); x1 ^= x0;
    x0 += x1; x1 = rotl32(x1, 15); x1 ^= x0;
    x0 += x1; x1 = rotl32(x1, 26); x1 ^= x0;
    x0 += x1; x1 = rotl32(x1,  6); x1 ^= x0;
    x0 += ks0; x1 += ks1 + 3u;
    x0 += x1; x1 = rotl32(x1, 17); x1 ^= x0;
    x0 += x1; x1 = rotl32(x1, 29); x1 ^= x0;
    x0 += x1; x1 = rotl32(x1, 16); x1 ^= x0;
    x0 += x1; x1 = rotl32(x1, 24); x1 ^= x0;
    x0 += ks1; x1 += ks2 + 4u;
    x0 += x1; x1 = rotl32(x1, 13); x1 ^= x0;
    x0 += x1; x1 = rotl32(x1, 15); x1 ^= x0;
    x0 += x1; x1 = rotl32(x1, 26); x1 ^= x0;
    x0 += x1; x1 = rotl32(x1,  6); x1 ^= x0;
    x0 += ks2; x1 += ks0 + 5u;

    return x0 ^ x1;
}

// ---------------- fp16 pack helpers ----------------
__device__ __forceinline__ uint32_t pack_h2(float a, float b) {
    __half2 h = __floats2half2_rn(a, b);
    return *reinterpret_cast<uint32_t*>(&h);
}
__device__ __forceinline__ uint4 pack_8(float4 a, float4 b) {
    return make_uint4(pack_h2(a.x, a.y), pack_h2(a.z, a.w),
                      pack_h2(b.x, b.y), pack_h2(b.z, b.w));
}
__device__ __forceinline__ float sumsq4(float4 v) {
    return v.x * v.x + v.y * v.y + v.z * v.z + v.w * v.w;
}

// ---------------- K1: scatter ∪ preamble — NO internal ordering ----------------
// blocks [0, SCAT_BLOCKS): dropout scatter into zero g_hidden + item mask set
// blocks [SCAT_BLOCKS, K1_BLOCKS): de convert -> fp16 + item reg norms (R8 layout)
__global__ void __launch_bounds__(256) k_scatter_pre(
        const int*   __restrict__ sp_row,
        const int*   __restrict__ sp_col,
        const float* __restrict__ en_emb,
        const int*   __restrict__ bat_items,
        const float* __restrict__ de_emb,
        const float* __restrict__ de_bias) {
    if (blockIdx.x < SCAT_BLOCKS) {
        int t    = blockIdx.x * blockDim.x + threadIdx.x;
        int i    = t >> 4;
        int lane = t & 15;
        int wl   = threadIdx.x & 31;

        uint32_t keep = 0;
        if (lane == 0) {
            uint32_t bits = threefry_bits((uint32_t)i);
            float u = __uint_as_float((bits >> 9) | 0x3f800000u) - 1.0f;
            keep = (u < 0.8f) ? 1u : 0u;
        }
        keep = __shfl_sync(0xffffffffu, keep, wl & 16, 32);

        if (t < N_PAIRS) g_mask[__ldg(bat_items + t)] = 1;   // mask zero by invariant
        if (!keep) return;

        int row = __ldg(sp_row + i);
        int col = __ldg(sp_col + i);
        float4 e = __ldg((const float4*)en_emb + (size_t)col * 16 + lane);
        float4 v = make_float4(1.25f * e.x, 1.25f * e.y, 1.25f * e.z, 1.25f * e.w);
        atomicAdd((float4*)(g_hidden + (size_t)row * 64 + lane * 4), v);  // hidden zero by invariant
    } else {
        int idx = (blockIdx.x - SCAT_BLOCKS) * blockDim.x + threadIdx.x;  // 0..799999 exact
        int row = idx >> 3;      // 8 threads per item row
        int l8  = idx & 7;

        float4 a  = __ldg((const float4*)de_emb + idx * 2);
        float4 b  = __ldg((const float4*)de_emb + idx * 2 + 1);
        float4 ea = __ldg((const float4*)en_emb + idx * 2);
        float4 eb = __ldg((const float4*)en_emb + idx * 2 + 1);

        ((uint4*)g_de_h)[idx] = pack_8(a, b);

        float c = sumsq4(a) + sumsq4(b) + sumsq4(ea) + sumsq4(eb);
        c += __shfl_xor_sync(0xffffffffu, c, 1);
        c += __shfl_xor_sync(0xffffffffu, c, 2);
        c += __shfl_xor_sync(0xffffffffu, c, 4);
        if (l8 == 0) {
            float bb = __ldg(de_bias + row);
            g_item_reg[row] = c + bb * bb;
        }
    }
}

// ---------------- K2: tanh(sum + user + offset) + fp16 copy + re-zero hidden ----------------
__global__ void __launch_bounds__(256) k_tanh(
        const int*   __restrict__ user_ids,
        const float* __restrict__ user_emb,
        const float* __restrict__ en_offset,
        float* reg_out) {
    int idx = blockIdx.x * blockDim.x + threadIdx.x;   // exact: B*D/8 = 32768
    int b  = idx >> 3;
    int d8 = idx & 7;   // handles elems d8*8 .. d8*8+7

    // independent input gathers BEFORE the dependency sync
    int uid = __ldg(user_ids + b);
    float4 u0 = __ldg((const float4*)user_emb + (size_t)uid * 16 + d8 * 2);
    float4 u1 = __ldg((const float4*)user_emb + (size_t)uid * 16 + d8 * 2 + 1);
    float4 o0 = __ldg((const float4*)en_offset + d8 * 2);
    float4 o1 = __ldg((const float4*)en_offset + d8 * 2 + 1);

    cudaGridDependencySynchronize();   // K1 scatter atomics complete

    float4 a = ((const float4*)g_hidden)[idx * 2];
    float4 c = ((const float4*)g_hidden)[idx * 2 + 1];
    a = make_float4(tanhf(a.x + u0.x + o0.x), tanhf(a.y + u0.y + o0.y),
                    tanhf(a.z + u0.z + o0.z), tanhf(a.w + u0.w + o0.w));
    c = make_float4(tanhf(c.x + u1.x + o1.x), tanhf(c.y + u1.y + o1.y),
                    tanhf(c.z + u1.z + o1.z), tanhf(c.w + u1.w + o1.w));
    ((uint4*)g_hidden_h)[idx] = pack_8(a, c);

    // restore the zero invariant for the next call
    ((float4*)g_hidden)[idx * 2]     = make_float4(0.f, 0.f, 0.f, 0.f);
    ((float4*)g_hidden)[idx * 2 + 1] = make_float4(0.f, 0.f, 0.f, 0.f);

    if (idx == 0 && reg_out) *reg_out = 0.0f;
}

// ---------------- K3: decode + reg tail (re-zeros g_mask) ----------------
__device__ __forceinline__ float dot8h(uint4 hv, uint4 ev) {
    float acc = 0.0f;
    const uint32_t* hw = (const uint32_t*)&hv;
    const uint32_t* ew = (const uint32_t*)&ev;
#pragma unroll
    for (int i = 0; i < 4; i++) {
        float2 f = __half22float2(*(const __half2*)&hw[i]);
        float2 g = __half22float2(*(const __half2*)&ew[i]);
        acc += f.x * g.x + f.y * g.y;
    }
    return acc;
}

__global__ void __launch_bounds__(256) k_decode_reg(
        const int* __restrict__ bat_idx,
        const int* __restrict__ bat_items,
        const float* __restrict__ de_bias,
        const float* __restrict__ en_offset,
        const float* __restrict__ user_emb,
        const int*   __restrict__ user_ids,
        float* __restrict__ out,
        float* __restrict__ reg_out) {
    if (blockIdx.x < DECODE_BLOCKS) {
        int t = blockIdx.x * blockDim.x + threadIdx.x;
        int g = t >> 3;             // group handles pairs 4g..4g+3
        int l = t & 7;

        int4 bb = __ldg((const int4*)bat_idx + g);
        int4 ii = __ldg((const int4*)bat_items + g);
        cudaGridDependencySynchronize();   // hidden_h (K2), de_h (K1)

        uint4 h0 = ((const uint4*)g_hidden_h + (size_t)bb.x * 8)[l];
        uint4 h1 = ((const uint4*)g_hidden_h + (size_t)bb.y * 8)[l];
        uint4 h2 = ((const uint4*)g_hidden_h + (size_t)bb.z * 8)[l];
        uint4 h3 = ((const uint4*)g_hidden_h + (size_t)bb.w * 8)[l];
        uint4 e0 = ((const uint4*)g_de_h + (size_t)ii.x * 8)[l];
        uint4 e1 = ((const uint4*)g_de_h + (size_t)ii.y * 8)[l];
        uint4 e2 = ((const uint4*)g_de_h + (size_t)ii.z * 8)[l];
        uint4 e3 = ((const uint4*)g_de_h + (size_t)ii.w * 8)[l];

        float p0 = dot8h(h0, e0);
        float p1 = dot8h(h1, e1);
        float p2 = dot8h(h2, e2);
        float p3 = dot8h(h3, e3);
#pragma unroll
        for (int s = 1; s <= 4; s <<= 1) {
            p0 += __shfl_xor_sync(0xffffffffu, p0, s);
            p1 += __shfl_xor_sync(0xffffffffu, p1, s);
            p2 += __shfl_xor_sync(0xffffffffu, p2, s);
            p3 += __shfl_xor_sync(0xffffffffu, p3, s);
        }
        if (l == 0) {
            float4 r = make_float4(p0 + __ldg(de_bias + ii.x),
                                   p1 + __ldg(de_bias + ii.y),
                                   p2 + __ldg(de_bias + ii.z),
                                   p3 + __ldg(de_bias + ii.w));
            ((float4*)out)[g] = r;
        }
    } else {
        cudaGridDependencySynchronize();
        __shared__ float bacc;
        if (threadIdx.x == 0) bacc = 0.0f;
        __syncthreads();

        int t = (blockIdx.x - DECODE_BLOCKS) * blockDim.x + threadIdx.x;
        float c = 0.0f;
        if (t < NUM_ITEMS_C) {
            c = g_mask[t] ? g_item_reg[t] : 0.0f;
            g_mask[t] = 0;   // restore the zero invariant
            if (t == 0) {
                for (int k = 0; k < D_DIM; k++) {
                    float o = __ldg(en_offset + k);
                    c += o * o;
                }
            }
        } else if (t >= ITEM_SEG && t < TAIL_THREADS) {
            int r = t - ITEM_SEG;
            int b = r >> 4, lane = r & 15;
            float4 u = __ldg((const float4*)user_emb + (size_t)__ldg(user_ids + b) * 16 + lane);
            c = sumsq4(u);
        }
#pragma unroll
        for (int s = 1; s <= 16; s <<= 1) c += __shfl_xor_sync(0xffffffffu, c, s);
        if ((threadIdx.x & 31) == 0 && c != 0.0f) atomicAdd(&bacc, c);
        __syncthreads();
        if (threadIdx.x == 0 && bacc != 0.0f && reg_out) atomicAdd(reg_out, 0.5f * bacc);
    }
}

// ---------------- launch ----------------
static void launch_pdl(void* fn, dim3 grid, void** args) {
    cudaLaunchConfig_t cfg = {};
    cfg.gridDim = grid;
    cfg.blockDim = dim3(256);
    cfg.dynamicSmemBytes = 0;
    cfg.stream = 0;
    cudaLaunchAttribute attr[1];
    attr[0].id = cudaLaunchAttributeProgrammaticStreamSerialization;
    attr[0].val.programmaticStreamSerializationAllowed = 1;
    cfg.attrs = attr;
    cfg.numAttrs = 1;
    cudaLaunchKernelExC(&cfg, fn, args);
}

extern "C" void kernel_launch(void* const* d_in, const int* in_sizes, int n_in,
                              void* d_out, int out_size) {
    const int*   user_ids  = (const int*)d_in[0];
    const int*   bat_idx   = (const int*)d_in[1];
    const int*   sp_row    = (const int*)d_in[2];
    const int*   sp_col    = (const int*)d_in[3];
    const int*   bat_items = (const int*)d_in[4];
    const float* en_emb    = (const float*)d_in[5];
    const float* en_offset = (const float*)d_in[6];
    const float* de_emb    = (const float*)d_in[7];
    const float* de_bias   = (const float*)d_in[8];
    const float* user_emb  = (const float*)d_in[9];
    float* out = (float*)d_out;
    float* reg_out = (out_size > N_PAIRS) ? (out + N_PAIRS) : nullptr;

    // K1: scatter + preamble fused, no internal dependency
    k_scatter_pre<<<K1_BLOCKS, 256>>>(sp_row, sp_col, en_emb, bat_items,
                                      de_emb, de_bias);
    // K2: tanh + user/offset add (PDL, same stream)
    {
        void* args[] = { (void*)&user_ids, (void*)&user_emb, (void*)&en_offset,
                         (void*)&reg_out };
        launch_pdl((void*)k_tanh, dim3(B_USERS * D_DIM / 8 / 256), args);
    }
    // K3: decode + reg tail (PDL, same stream)
    {
        void* args[] = { (void*)&bat_idx, (void*)&bat_items, (void*)&de_bias,
                         (void*)&en_offset, (void*)&user_emb, (void*)&user_ids,
                         (void*)&out, (void*)&reg_out };
        launch_pdl((void*)k_decode_reg, dim3(DECODE_BLOCKS + TAIL_BLOCKS), args);
    }
}